// round 12
// baseline (speedup 1.0000x reference)
#include <cuda_runtime.h>
#include <cuda_fp16.h>
#include <cstdint>
#include <math.h>

// Problem constants
constexpr int B_  = 8;
constexpr int C_  = 256;
constexpr int H_  = 31;
constexpr int W_  = 31;
constexpr int T_  = 7;
constexpr int K_  = 49;      // T*T
constexpr int OC_ = 147;     // 3*K
constexpr int NP_ = 74;      // oc pairs (padded 148)
constexpr int OH_ = 25;
constexpr int OW_ = 25;
constexpr int HW_ = H_ * W_; // 961
constexpr int OHW_= OH_ * OW_; // 625
constexpr int CT_ = 4;       // C split tiles
constexpr int CPT_= C_ / CT_;// 64 channels per tile
constexpr int YT_ = 9;       // y tiles of 3 rows

// Scratch (device globals; no allocations allowed)
__device__ __half g_srH[B_ * HW_ * C_];                // (B,H,W,C) fp16
__device__ float  g_tmplT[B_ * K_ * C_];               // (B,K,C) fp32
__device__ float  g_om[B_ * OC_ * OHW_];               // reduced conv out
__device__ float  g_part[CT_ * B_ * OC_ * OHW_];       // conv partials
__device__ float2 g_wpk[C_ * NP_ * 9];                 // packed weights [c][pair][tap]

// packed f32x2 helpers
#define FMA_F32X2(d, a, b, c) \
    asm("fma.rn.f32x2 %0, %1, %2, %3;" : "=l"(d) : "l"(a), "l"(b), "l"(c))
#define PACK_DUP(d, v) \
    asm("mov.b64 %0, {%1, %1};" : "=l"(d) : "f"(v))
#define UNPACK2(lo, hi, p) \
    asm("mov.b64 {%0, %1}, %2;" : "=f"(lo), "=f"(hi) : "l"(p))

__device__ __forceinline__ __half2 u2h(unsigned int u) {
    return *reinterpret_cast<const __half2*>(&u);
}

// ---------------------------------------------------------------------------
// Fused prep: transpose sr (->fp16), transpose tmpl (fp32), pack weights.
// ---------------------------------------------------------------------------
constexpr int PREP_SR_BLKS   = 31 * 8 * 8;                   // 1984
constexpr int PREP_TMPL_BLKS = (B_ * K_ * C_ + 255) / 256;   // 392
constexpr int PREP_PACK_BLKS = (C_ * NP_ * 9 + 255) / 256;   // 666
constexpr int PREP_BLKS = PREP_SR_BLKS + PREP_TMPL_BLKS + PREP_PACK_BLKS;

__global__ void __launch_bounds__(256) prep_kernel(
    const float* __restrict__ sr,
    const float* __restrict__ tmpl,
    const float* __restrict__ w)
{
    __shared__ float tile[32][33];
    const int bid = blockIdx.x;
    const int tid = threadIdx.x;

    if (bid < PREP_SR_BLKS) {
        int px = bid % 31;
        int cy = (bid / 31) % 8;
        int b  = bid / (31 * 8);
        int p0 = px * 32, c0 = cy * 32;
        int tx = tid % 32, ty = tid / 32;
        #pragma unroll
        for (int yy = 0; yy < 32; yy += 8) {
            int c = c0 + ty + yy, p = p0 + tx;
            if (p < HW_) tile[ty + yy][tx] = sr[(b * C_ + c) * HW_ + p];
        }
        __syncthreads();
        #pragma unroll
        for (int yy = 0; yy < 32; yy += 8) {
            int p = p0 + ty + yy, c = c0 + tx;
            if (p < HW_) g_srH[(b * HW_ + p) * C_ + c] = __float2half(tile[tx][ty + yy]);
        }
    } else if (bid < PREP_SR_BLKS + PREP_TMPL_BLKS) {
        int t = (bid - PREP_SR_BLKS) * 256 + tid;
        if (t < B_ * K_ * C_) {
            int c = t % C_;
            int k = (t / C_) % K_;
            int b = t / (C_ * K_);
            g_tmplT[t] = tmpl[(b * C_ + c) * K_ + k];
        }
    } else {
        int t = (bid - PREP_SR_BLKS - PREP_TMPL_BLKS) * 256 + tid;
        if (t < C_ * NP_ * 9) {
            int tap = t % 9;
            int p   = (t / 9) % NP_;
            int c   = t / (9 * NP_);
            int o0 = 2 * p, o1 = 2 * p + 1;
            float v0 = w[o0 * (C_ * 9) + c * 9 + tap];
            float v1 = (o1 < OC_) ? w[o1 * (C_ * 9) + c * 9 + tap] : 0.0f;
            g_wpk[t] = make_float2(v0, v1);
        }
    }
}

// ---------------------------------------------------------------------------
// K2: 3x3 conv (validated form). grid=(9,8,4)=288 blocks, 1 wave.
// ---------------------------------------------------------------------------
__global__ void __launch_bounds__(384, 2) conv_om_kernel(
    const float* __restrict__ sr)
{
    __shared__ float s_sr[CPT_][5][33];   // 42.2 KB

    const int by = blockIdx.x;
    const int b  = blockIdx.y;
    const int ct = blockIdx.z;
    const int tid = threadIdx.x;

    const int og = tid / 5;
    const int xg = tid % 5;
    const bool active = (og < NP_);
    const int x_base = xg * 5;
    const int y_base = by * 3;
    const int cbase  = ct * CPT_;

    for (int e = tid; e < CPT_ * 5 * 33; e += 384) {
        int cc  = e / 165;
        int rem = e % 165;
        int r   = rem / 33;
        int xp  = rem % 33;
        int gy  = y_base + r - 1;
        int gx  = xp - 1;
        float v = 0.f;
        if (gy >= 0 && gy < H_ && gx >= 0 && gx < W_)
            v = sr[((b * C_ + cbase + cc) * H_ + gy) * W_ + gx];
        s_sr[cc][r][xp] = v;
    }
    __syncthreads();

    unsigned long long acc[3][5];
    #pragma unroll
    for (int yy = 0; yy < 3; yy++)
        #pragma unroll
        for (int xx = 0; xx < 5; xx++) acc[yy][xx] = 0ull;

    if (active) {
        const unsigned long long* __restrict__ wp0 =
            (const unsigned long long*)g_wpk + (size_t)og * 9;
        #pragma unroll 2
        for (int c = 0; c < CPT_; c++) {
            unsigned long long wq[9];
            const unsigned long long* wp = wp0 + (size_t)(cbase + c) * (NP_ * 9);
            #pragma unroll
            for (int t = 0; t < 9; t++) wq[t] = __ldg(wp + t);

            #pragma unroll
            for (int ir = 0; ir < 5; ir++) {
                #pragma unroll
                for (int u = 0; u < 7; u++) {
                    unsigned long long rp;
                    {
                        float v = s_sr[c][ir][x_base + u];
                        PACK_DUP(rp, v);
                    }
                    #pragma unroll
                    for (int dx = 0; dx < 3; dx++) {
                        const int xx = u - dx;
                        if (xx >= 0 && xx < 5) {
                            #pragma unroll
                            for (int dy = 0; dy < 3; dy++) {
                                const int yy = ir - dy;
                                if (yy >= 0 && yy < 3)
                                    FMA_F32X2(acc[yy][xx], rp,
                                              wq[dy * 3 + dx], acc[yy][xx]);
                            }
                        }
                    }
                }
            }
        }

        int o_even = og * 2;
        #pragma unroll
        for (int yy = 0; yy < 3; yy++) {
            int y = y_base + yy;
            if (y >= OH_) continue;
            #pragma unroll
            for (int xx = 0; xx < 5; xx++) {
                float lo, hi;
                UNPACK2(lo, hi, acc[yy][xx]);
                int base = ct * (B_ * OC_ * OHW_) +
                           (b * OC_ + o_even) * OHW_ + y * OW_ + x_base + xx;
                g_part[base] = lo;
                if (o_even + 1 < OC_) g_part[base + OHW_] = hi;
            }
        }
    }
}

// sum partials + bias -> g_om
__global__ void reduce_om_kernel(const float* __restrict__ bias) {
    int t = blockIdx.x * 256 + threadIdx.x;
    if (t < B_ * OC_ * OHW_) {
        int oc = (t / OHW_) % OC_;
        float s = bias[oc];
        #pragma unroll
        for (int ct = 0; ct < CT_; ct++)
            s += g_part[ct * (B_ * OC_ * OHW_) + t];
        g_om[t] = s;
    }
}

// ---------------------------------------------------------------------------
// K3: deformable bilinear gather + weighted correlation (v3).
// Warp-level layout: block = 256 threads = 4 positions x 2 k-halves x 32 lanes.
// Lane = 8 channels (LDG.128 fp16 corners). Bilinear+mask in half2;
// template product + accumulation in fp32 (tmpl fp32). k split across 2
// warps per position; fixed-order fp32 combine via smem (deterministic).
// ---------------------------------------------------------------------------
__global__ void __launch_bounds__(256) deform_xcorr_kernel(float* __restrict__ out)
{
    __shared__ int4  sA4[4][K_];    // corner byte offsets (fp16 array)
    __shared__ uint4 sWh[4][K_];    // duplicated half2 weights
    __shared__ float s_red[4][256]; // cross-warp partial sums

    const int tid = threadIdx.x;

    if (tid < 4 * K_) {
        const int g2 = tid / K_;
        const int k  = tid % K_;
        const int p  = blockIdx.x * 4 + g2;
        const int b  = p / OHW_;
        const int rem = p % OHW_;
        const int i  = rem / OW_;
        const int j  = rem % OW_;

        const int base = (b * OC_ + k) * OHW_ + i * OW_ + j;
        float oy = g_om[base];
        float ox = g_om[base + 49 * OHW_];
        float mz = g_om[base + 98 * OHW_];
        float m  = 1.0f / (1.0f + __expf(-mz));

        float ys = (float)i + (float)(k / T_) + oy;
        float xs = (float)j + (float)(k % T_) + ox;
        float y0f = floorf(ys), x0f = floorf(xs);
        float wy = ys - y0f, wx = xs - x0f;
        float y1f = y0f + 1.0f, x1f = x0f + 1.0f;

        bool vy0 = (y0f >= 0.0f) && (y0f <= (float)(H_ - 1));
        bool vy1 = (y1f >= 0.0f) && (y1f <= (float)(H_ - 1));
        bool vx0 = (x0f >= 0.0f) && (x0f <= (float)(W_ - 1));
        bool vx1 = (x1f >= 0.0f) && (x1f <= (float)(W_ - 1));

        float w00 = (1.0f - wy) * (1.0f - wx) * m; if (!(vy0 && vx0)) w00 = 0.0f;
        float w01 = (1.0f - wy) * wx          * m; if (!(vy0 && vx1)) w01 = 0.0f;
        float w10 = wy          * (1.0f - wx) * m; if (!(vy1 && vx0)) w10 = 0.0f;
        float w11 = wy          * wx          * m; if (!(vy1 && vx1)) w11 = 0.0f;

        int y0 = (int)fminf(fmaxf(y0f, 0.0f), (float)(H_ - 1));
        int y1 = (int)fminf(fmaxf(y1f, 0.0f), (float)(H_ - 1));
        int x0 = (int)fminf(fmaxf(x0f, 0.0f), (float)(W_ - 1));
        int x1 = (int)fminf(fmaxf(x1f, 0.0f), (float)(W_ - 1));

        sA4[g2][k] = make_int4((y0 * W_ + x0) * (C_ * 2),
                               (y0 * W_ + x1) * (C_ * 2),
                               (y1 * W_ + x0) * (C_ * 2),
                               (y1 * W_ + x1) * (C_ * 2));
        __half2 h00 = __float2half2_rn(w00);
        __half2 h01 = __float2half2_rn(w01);
        __half2 h10 = __float2half2_rn(w10);
        __half2 h11 = __float2half2_rn(w11);
        sWh[g2][k] = make_uint4(*reinterpret_cast<unsigned int*>(&h00),
                                *reinterpret_cast<unsigned int*>(&h01),
                                *reinterpret_cast<unsigned int*>(&h10),
                                *reinterpret_cast<unsigned int*>(&h11));
    }
    __syncthreads();

    const int w  = tid / 32;      // warp 0..7
    const int g  = w / 2;         // position slot 0..3
    const int h  = w & 1;         // k-half
    const int l  = tid % 32;      // lane = 8 channels
    const int p  = blockIdx.x * 4 + g;
    const int b  = p / OHW_;
    const int rem = p % OHW_;
    const int i  = rem / OW_;
    const int j  = rem % OW_;

    const char* srHb = (const char*)g_srH + ((size_t)b * HW_ * C_) * 2 + l * 16;
    const float4* tTb4 = (const float4*)(g_tmplT + (size_t)b * K_ * C_) + l * 2;

    float acc[8];
    #pragma unroll
    for (int q = 0; q < 8; q++) acc[q] = 0.0f;

    const int kb = h ? 25 : 0;
    const int ke = h ? 49 : 25;

    #pragma unroll 5
    for (int k = kb; k < ke; k++) {
        int4  a  = sA4[g][k];
        uint4 wh = sWh[g][k];
        __half2 w00 = u2h(wh.x), w01 = u2h(wh.y), w10 = u2h(wh.z), w11 = u2h(wh.w);

        uint4 u00 = *(const uint4*)(srHb + a.x);
        uint4 u01 = *(const uint4*)(srHb + a.y);
        uint4 u10 = *(const uint4*)(srHb + a.z);
        uint4 u11 = *(const uint4*)(srHb + a.w);
        float4 t0 = tTb4[k * 64];
        float4 t1 = tTb4[k * 64 + 1];

        __half2 v0 = __hmul2(w00, u2h(u00.x));
        v0 = __hfma2(w01, u2h(u01.x), v0);
        v0 = __hfma2(w10, u2h(u10.x), v0);
        v0 = __hfma2(w11, u2h(u11.x), v0);
        __half2 v1 = __hmul2(w00, u2h(u00.y));
        v1 = __hfma2(w01, u2h(u01.y), v1);
        v1 = __hfma2(w10, u2h(u10.y), v1);
        v1 = __hfma2(w11, u2h(u11.y), v1);
        __half2 v2 = __hmul2(w00, u2h(u00.z));
        v2 = __hfma2(w01, u2h(u01.z), v2);
        v2 = __hfma2(w10, u2h(u10.z), v2);
        v2 = __hfma2(w11, u2h(u11.z), v2);
        __half2 v3 = __hmul2(w00, u2h(u00.w));
        v3 = __hfma2(w01, u2h(u01.w), v3);
        v3 = __hfma2(w10, u2h(u10.w), v3);
        v3 = __hfma2(w11, u2h(u11.w), v3);

        float2 f0 = __half22float2(v0);
        float2 f1 = __half22float2(v1);
        float2 f2 = __half22float2(v2);
        float2 f3 = __half22float2(v3);

        acc[0] = fmaf(t0.x, f0.x, acc[0]);
        acc[1] = fmaf(t0.y, f0.y, acc[1]);
        acc[2] = fmaf(t0.z, f1.x, acc[2]);
        acc[3] = fmaf(t0.w, f1.y, acc[3]);
        acc[4] = fmaf(t1.x, f2.x, acc[4]);
        acc[5] = fmaf(t1.y, f2.y, acc[5]);
        acc[6] = fmaf(t1.z, f3.x, acc[6]);
        acc[7] = fmaf(t1.w, f3.y, acc[7]);
    }

    // combine the two k-halves (fixed order -> deterministic)
    if (h == 1) {
        #pragma unroll
        for (int q = 0; q < 8; q++) s_red[g][l * 8 + q] = acc[q];
    }
    __syncthreads();
    if (h == 0) {
        #pragma unroll
        for (int q = 0; q < 8; q++) acc[q] += s_red[g][l * 8 + q];

        const int c = l * 8;
        float* op = out + ((size_t)(b * C_ + c) * OH_ + i) * OW_ + j;
        #pragma unroll
        for (int q = 0; q < 8; q++)
            op[q * OHW_] = acc[q];
    }
}

// ---------------------------------------------------------------------------
extern "C" void kernel_launch(void* const* d_in, const int* in_sizes, int n_in,
                              void* d_out, int out_size)
{
    const float* sr   = (const float*)d_in[0];
    const float* tmpl = (const float*)d_in[1];
    const float* w    = (const float*)d_in[2];
    const float* bias = (const float*)d_in[3];
    float* out = (float*)d_out;

    prep_kernel<<<PREP_BLKS, 256>>>(sr, tmpl, w);
    {
        dim3 g(YT_, B_, CT_);
        conv_om_kernel<<<g, 384>>>(sr);
    }
    {
        int n = B_ * OC_ * OHW_;
        reduce_om_kernel<<<(n + 255) / 256, 256>>>(bias);
    }
    {
        deform_xcorr_kernel<<<1250, 256>>>(out);
    }
}

// round 13
// speedup vs baseline: 1.0481x; 1.0481x over previous
#include <cuda_runtime.h>
#include <cuda_fp16.h>
#include <cstdint>
#include <math.h>

// Problem constants
constexpr int B_  = 8;
constexpr int C_  = 256;
constexpr int H_  = 31;
constexpr int W_  = 31;
constexpr int T_  = 7;
constexpr int K_  = 49;      // T*T
constexpr int OC_ = 147;     // 3*K
constexpr int NP_ = 74;      // oc pairs (padded 148)
constexpr int OH_ = 25;
constexpr int OW_ = 25;
constexpr int HW_ = H_ * W_; // 961
constexpr int OHW_= OH_ * OW_; // 625
constexpr int CT_ = 4;       // C split tiles
constexpr int CPT_= C_ / CT_;// 64 channels per tile
constexpr int YT_ = 9;       // y tiles of 3 rows

// Scratch (device globals; no allocations allowed)
__device__ __half g_srH[B_ * HW_ * C_];                // (B,H,W,C) fp16
__device__ __half g_tmplH[B_ * K_ * C_];               // (B,K,C) fp16
__device__ float  g_om[B_ * OC_ * OHW_];               // reduced conv out
__device__ float  g_part[CT_ * B_ * OC_ * OHW_];       // conv partials
__device__ float2 g_wpk[C_ * NP_ * 9];                 // packed weights [c][pair][tap]

// packed f32x2 helpers
#define FMA_F32X2(d, a, b, c) \
    asm("fma.rn.f32x2 %0, %1, %2, %3;" : "=l"(d) : "l"(a), "l"(b), "l"(c))
#define PACK_DUP(d, v) \
    asm("mov.b64 %0, {%1, %1};" : "=l"(d) : "f"(v))
#define UNPACK2(lo, hi, p) \
    asm("mov.b64 {%0, %1}, %2;" : "=f"(lo), "=f"(hi) : "l"(p))

__device__ __forceinline__ __half2 u2h(unsigned int u) {
    return *reinterpret_cast<const __half2*>(&u);
}

// ---------------------------------------------------------------------------
// Fused prep: transpose sr (->fp16), transpose tmpl (->fp16), pack weights.
// ---------------------------------------------------------------------------
constexpr int PREP_SR_BLKS   = 31 * 8 * 8;                   // 1984
constexpr int PREP_TMPL_BLKS = (B_ * K_ * C_ + 255) / 256;   // 392
constexpr int PREP_PACK_BLKS = (C_ * NP_ * 9 + 255) / 256;   // 666
constexpr int PREP_BLKS = PREP_SR_BLKS + PREP_TMPL_BLKS + PREP_PACK_BLKS;

__global__ void __launch_bounds__(256) prep_kernel(
    const float* __restrict__ sr,
    const float* __restrict__ tmpl,
    const float* __restrict__ w)
{
    __shared__ float tile[32][33];
    const int bid = blockIdx.x;
    const int tid = threadIdx.x;

    if (bid < PREP_SR_BLKS) {
        int px = bid % 31;
        int cy = (bid / 31) % 8;
        int b  = bid / (31 * 8);
        int p0 = px * 32, c0 = cy * 32;
        int tx = tid % 32, ty = tid / 32;
        #pragma unroll
        for (int yy = 0; yy < 32; yy += 8) {
            int c = c0 + ty + yy, p = p0 + tx;
            if (p < HW_) tile[ty + yy][tx] = sr[(b * C_ + c) * HW_ + p];
        }
        __syncthreads();
        #pragma unroll
        for (int yy = 0; yy < 32; yy += 8) {
            int p = p0 + ty + yy, c = c0 + tx;
            if (p < HW_) g_srH[(b * HW_ + p) * C_ + c] = __float2half(tile[tx][ty + yy]);
        }
    } else if (bid < PREP_SR_BLKS + PREP_TMPL_BLKS) {
        int t = (bid - PREP_SR_BLKS) * 256 + tid;
        if (t < B_ * K_ * C_) {
            int c = t % C_;
            int k = (t / C_) % K_;
            int b = t / (C_ * K_);
            g_tmplH[t] = __float2half(tmpl[(b * C_ + c) * K_ + k]);
        }
    } else {
        int t = (bid - PREP_SR_BLKS - PREP_TMPL_BLKS) * 256 + tid;
        if (t < C_ * NP_ * 9) {
            int tap = t % 9;
            int p   = (t / 9) % NP_;
            int c   = t / (9 * NP_);
            int o0 = 2 * p, o1 = 2 * p + 1;
            float v0 = w[o0 * (C_ * 9) + c * 9 + tap];
            float v1 = (o1 < OC_) ? w[o1 * (C_ * 9) + c * 9 + tap] : 0.0f;
            g_wpk[t] = make_float2(v0, v1);
        }
    }
}

// ---------------------------------------------------------------------------
// K2: 3x3 conv (validated form). grid=(9,8,4)=288 blocks, 1 wave.
// ---------------------------------------------------------------------------
__global__ void __launch_bounds__(384, 2) conv_om_kernel(
    const float* __restrict__ sr)
{
    __shared__ float s_sr[CPT_][5][33];   // 42.2 KB

    const int by = blockIdx.x;
    const int b  = blockIdx.y;
    const int ct = blockIdx.z;
    const int tid = threadIdx.x;

    const int og = tid / 5;
    const int xg = tid % 5;
    const bool active = (og < NP_);
    const int x_base = xg * 5;
    const int y_base = by * 3;
    const int cbase  = ct * CPT_;

    for (int e = tid; e < CPT_ * 5 * 33; e += 384) {
        int cc  = e / 165;
        int rem = e % 165;
        int r   = rem / 33;
        int xp  = rem % 33;
        int gy  = y_base + r - 1;
        int gx  = xp - 1;
        float v = 0.f;
        if (gy >= 0 && gy < H_ && gx >= 0 && gx < W_)
            v = sr[((b * C_ + cbase + cc) * H_ + gy) * W_ + gx];
        s_sr[cc][r][xp] = v;
    }
    __syncthreads();

    unsigned long long acc[3][5];
    #pragma unroll
    for (int yy = 0; yy < 3; yy++)
        #pragma unroll
        for (int xx = 0; xx < 5; xx++) acc[yy][xx] = 0ull;

    if (active) {
        const unsigned long long* __restrict__ wp0 =
            (const unsigned long long*)g_wpk + (size_t)og * 9;
        #pragma unroll 2
        for (int c = 0; c < CPT_; c++) {
            unsigned long long wq[9];
            const unsigned long long* wp = wp0 + (size_t)(cbase + c) * (NP_ * 9);
            #pragma unroll
            for (int t = 0; t < 9; t++) wq[t] = __ldg(wp + t);

            #pragma unroll
            for (int ir = 0; ir < 5; ir++) {
                #pragma unroll
                for (int u = 0; u < 7; u++) {
                    unsigned long long rp;
                    {
                        float v = s_sr[c][ir][x_base + u];
                        PACK_DUP(rp, v);
                    }
                    #pragma unroll
                    for (int dx = 0; dx < 3; dx++) {
                        const int xx = u - dx;
                        if (xx >= 0 && xx < 5) {
                            #pragma unroll
                            for (int dy = 0; dy < 3; dy++) {
                                const int yy = ir - dy;
                                if (yy >= 0 && yy < 3)
                                    FMA_F32X2(acc[yy][xx], rp,
                                              wq[dy * 3 + dx], acc[yy][xx]);
                            }
                        }
                    }
                }
            }
        }

        int o_even = og * 2;
        #pragma unroll
        for (int yy = 0; yy < 3; yy++) {
            int y = y_base + yy;
            if (y >= OH_) continue;
            #pragma unroll
            for (int xx = 0; xx < 5; xx++) {
                float lo, hi;
                UNPACK2(lo, hi, acc[yy][xx]);
                int base = ct * (B_ * OC_ * OHW_) +
                           (b * OC_ + o_even) * OHW_ + y * OW_ + x_base + xx;
                g_part[base] = lo;
                if (o_even + 1 < OC_) g_part[base + OHW_] = hi;
            }
        }
    }
}

// sum partials + bias -> g_om
__global__ void reduce_om_kernel(const float* __restrict__ bias) {
    int t = blockIdx.x * 256 + threadIdx.x;
    if (t < B_ * OC_ * OHW_) {
        int oc = (t / OHW_) % OC_;
        float s = bias[oc];
        #pragma unroll
        for (int ct = 0; ct < CT_; ct++)
            s += g_part[ct * (B_ * OC_ * OHW_) + t];
        g_om[t] = s;
    }
}

// ---------------------------------------------------------------------------
// K3: deformable bilinear gather + weighted correlation (v4).
// block = 256 = 8 warps = 8 positions; lane = 8 channels (LDG.128 fp16).
// Bilinear+mask in half2; template (fp16->fp32) product + accum in fp32.
// grid = 625 (5000 positions / 8).
// ---------------------------------------------------------------------------
__global__ void __launch_bounds__(256) deform_xcorr_kernel(float* __restrict__ out)
{
    __shared__ int4  sA4[8][K_];    // corner byte offsets (fp16 array)
    __shared__ uint4 sWh[8][K_];    // duplicated half2 weights

    const int tid = threadIdx.x;

    for (int e = tid; e < 8 * K_; e += 256) {
        const int g2 = e / K_;
        const int k  = e % K_;
        const int p  = blockIdx.x * 8 + g2;
        const int b  = p / OHW_;
        const int rem = p % OHW_;
        const int i  = rem / OW_;
        const int j  = rem % OW_;

        const int base = (b * OC_ + k) * OHW_ + i * OW_ + j;
        float oy = g_om[base];
        float ox = g_om[base + 49 * OHW_];
        float mz = g_om[base + 98 * OHW_];
        float m  = 1.0f / (1.0f + __expf(-mz));

        float ys = (float)i + (float)(k / T_) + oy;
        float xs = (float)j + (float)(k % T_) + ox;
        float y0f = floorf(ys), x0f = floorf(xs);
        float wy = ys - y0f, wx = xs - x0f;
        float y1f = y0f + 1.0f, x1f = x0f + 1.0f;

        bool vy0 = (y0f >= 0.0f) && (y0f <= (float)(H_ - 1));
        bool vy1 = (y1f >= 0.0f) && (y1f <= (float)(H_ - 1));
        bool vx0 = (x0f >= 0.0f) && (x0f <= (float)(W_ - 1));
        bool vx1 = (x1f >= 0.0f) && (x1f <= (float)(W_ - 1));

        float w00 = (1.0f - wy) * (1.0f - wx) * m; if (!(vy0 && vx0)) w00 = 0.0f;
        float w01 = (1.0f - wy) * wx          * m; if (!(vy0 && vx1)) w01 = 0.0f;
        float w10 = wy          * (1.0f - wx) * m; if (!(vy1 && vx0)) w10 = 0.0f;
        float w11 = wy          * wx          * m; if (!(vy1 && vx1)) w11 = 0.0f;

        int y0 = (int)fminf(fmaxf(y0f, 0.0f), (float)(H_ - 1));
        int y1 = (int)fminf(fmaxf(y1f, 0.0f), (float)(H_ - 1));
        int x0 = (int)fminf(fmaxf(x0f, 0.0f), (float)(W_ - 1));
        int x1 = (int)fminf(fmaxf(x1f, 0.0f), (float)(W_ - 1));

        sA4[g2][k] = make_int4((y0 * W_ + x0) * (C_ * 2),
                               (y0 * W_ + x1) * (C_ * 2),
                               (y1 * W_ + x0) * (C_ * 2),
                               (y1 * W_ + x1) * (C_ * 2));
        __half2 h00 = __float2half2_rn(w00);
        __half2 h01 = __float2half2_rn(w01);
        __half2 h10 = __float2half2_rn(w10);
        __half2 h11 = __float2half2_rn(w11);
        sWh[g2][k] = make_uint4(*reinterpret_cast<unsigned int*>(&h00),
                                *reinterpret_cast<unsigned int*>(&h01),
                                *reinterpret_cast<unsigned int*>(&h10),
                                *reinterpret_cast<unsigned int*>(&h11));
    }
    __syncthreads();

    const int g  = tid / 32;      // warp -> position slot 0..7
    const int l  = tid % 32;      // lane = 8 channels
    const int p  = blockIdx.x * 8 + g;
    const int b  = p / OHW_;
    const int rem = p % OHW_;
    const int i  = rem / OW_;
    const int j  = rem % OW_;

    const char* srHb = (const char*)g_srH + ((size_t)b * HW_ * C_) * 2 + l * 16;
    const char* tHb  = (const char*)g_tmplH + ((size_t)b * K_ * C_) * 2 + l * 16;

    float acc[8];
    #pragma unroll
    for (int q = 0; q < 8; q++) acc[q] = 0.0f;

    #pragma unroll 7
    for (int k = 0; k < K_; k++) {
        int4  a  = sA4[g][k];
        uint4 wh = sWh[g][k];
        __half2 w00 = u2h(wh.x), w01 = u2h(wh.y), w10 = u2h(wh.z), w11 = u2h(wh.w);

        uint4 u00 = *(const uint4*)(srHb + a.x);
        uint4 u01 = *(const uint4*)(srHb + a.y);
        uint4 u10 = *(const uint4*)(srHb + a.z);
        uint4 u11 = *(const uint4*)(srHb + a.w);
        uint4 ut  = *(const uint4*)(tHb + k * (C_ * 2));

        __half2 v0 = __hmul2(w00, u2h(u00.x));
        v0 = __hfma2(w01, u2h(u01.x), v0);
        v0 = __hfma2(w10, u2h(u10.x), v0);
        v0 = __hfma2(w11, u2h(u11.x), v0);
        __half2 v1 = __hmul2(w00, u2h(u00.y));
        v1 = __hfma2(w01, u2h(u01.y), v1);
        v1 = __hfma2(w10, u2h(u10.y), v1);
        v1 = __hfma2(w11, u2h(u11.y), v1);
        __half2 v2 = __hmul2(w00, u2h(u00.z));
        v2 = __hfma2(w01, u2h(u01.z), v2);
        v2 = __hfma2(w10, u2h(u10.z), v2);
        v2 = __hfma2(w11, u2h(u11.z), v2);
        __half2 v3 = __hmul2(w00, u2h(u00.w));
        v3 = __hfma2(w01, u2h(u01.w), v3);
        v3 = __hfma2(w10, u2h(u10.w), v3);
        v3 = __hfma2(w11, u2h(u11.w), v3);

        float2 f0 = __half22float2(v0);
        float2 f1 = __half22float2(v1);
        float2 f2 = __half22float2(v2);
        float2 f3 = __half22float2(v3);
        float2 t0 = __half22float2(u2h(ut.x));
        float2 t1 = __half22float2(u2h(ut.y));
        float2 t2 = __half22float2(u2h(ut.z));
        float2 t3 = __half22float2(u2h(ut.w));

        acc[0] = fmaf(t0.x, f0.x, acc[0]);
        acc[1] = fmaf(t0.y, f0.y, acc[1]);
        acc[2] = fmaf(t1.x, f1.x, acc[2]);
        acc[3] = fmaf(t1.y, f1.y, acc[3]);
        acc[4] = fmaf(t2.x, f2.x, acc[4]);
        acc[5] = fmaf(t2.y, f2.y, acc[5]);
        acc[6] = fmaf(t3.x, f3.x, acc[6]);
        acc[7] = fmaf(t3.y, f3.y, acc[7]);
    }

    const int c = l * 8;
    float* op = out + ((size_t)(b * C_ + c) * OH_ + i) * OW_ + j;
    #pragma unroll
    for (int q = 0; q < 8; q++)
        op[q * OHW_] = acc[q];
}

// ---------------------------------------------------------------------------
extern "C" void kernel_launch(void* const* d_in, const int* in_sizes, int n_in,
                              void* d_out, int out_size)
{
    const float* sr   = (const float*)d_in[0];
    const float* tmpl = (const float*)d_in[1];
    const float* w    = (const float*)d_in[2];
    const float* bias = (const float*)d_in[3];
    float* out = (float*)d_out;

    prep_kernel<<<PREP_BLKS, 256>>>(sr, tmpl, w);
    {
        dim3 g(YT_, B_, CT_);
        conv_om_kernel<<<g, 384>>>(sr);
    }
    {
        int n = B_ * OC_ * OHW_;
        reduce_om_kernel<<<(n + 255) / 256, 256>>>(bias);
    }
    {
        deform_xcorr_kernel<<<625, 256>>>(out);
    }
}